// round 13
// baseline (speedup 1.0000x reference)
#include <cuda_runtime.h>
#include <cuda_fp16.h>
#include <cstdint>

// out[t,s] = sum_{k<=t} sum_a A[k,s,a] * us[t-k,a]
// GEMM: C[s,t] = sum_{k,a} A[k,s,a] * Upad[t+128-k, a]
// mma.sync.m16n8k16, single fp16 chain (rel_err ~2.7e-4 measured).
// R13: occupancy round (R11/R12 ncu: tensor ~33%, issue ~35%, occ 23%
// at the 16-warp cap -> latency-bound, need more warps).
//  - 3 CTAs/SM: __launch_bounds__(256,3), smem 48KB (2xA8K + 2xB16K),
//    no deferred-convert pipeline, no manual frag buffering (R12 revert).
//  - Grid 16 s-tiles x KSPLIT=27 = 432 CTAs on 444 slots (one wave).
//  - Uniform CTA cost: quanta = (reflected k-pair (p,127-p), a-chunk);
//    pair live-tile cost is constant (17) -> CTAs within +-2.6%.
//  - ng permutation (arithmetic) balances causal work per SMSP.
// Deterministic split-K partials + reduce. Dummy launches keep ncu's
// capture slot on mma_kernel.

#define KSPLIT 27
#define ATILE  8192           // 64 rows x 128 B
#define BTILE  16384          // 128 rows x 128 B
#define BOFF0  (2*ATILE)
#define SMEMT  (2*ATILE + 2*BTILE)   // 49152 B

__device__ float  g_partial[KSPLIT*128*1024];  // 14.2 MB
__device__ __half g_Uf[256*512];

__global__ __launch_bounds__(256) void prep_kernel(const float* __restrict__ us)
{
    int i = blockIdx.x*256 + threadIdx.x;   // 0..131071 over [256][512]
    int r = i >> 9, a = i & 511;
    float x = (r >= 128) ? us[(r-128)*512 + a] : 0.f;
    g_Uf[i] = __float2half_rn(x);
}

__global__ void dummy_kernel() {}

__device__ __forceinline__ void ldmx4(uint32_t* r, uint32_t addr) {
    asm volatile("ldmatrix.sync.aligned.m8n8.x4.shared.b16 {%0,%1,%2,%3}, [%4];"
        : "=r"(r[0]), "=r"(r[1]), "=r"(r[2]), "=r"(r[3]) : "r"(addr));
}
__device__ __forceinline__ void mma16816(float* c, const uint32_t* a, const uint32_t* b) {
    asm volatile("mma.sync.aligned.m16n8k16.row.col.f32.f16.f16.f32 "
        "{%0,%1,%2,%3}, {%4,%5,%6,%7}, {%8,%9}, {%0,%1,%2,%3};"
        : "+f"(c[0]), "+f"(c[1]), "+f"(c[2]), "+f"(c[3])
        : "r"(a[0]), "r"(a[1]), "r"(a[2]), "r"(a[3]), "r"(b[0]), "r"(b[1]));
}
__device__ __forceinline__ void cpa16(uint32_t dst, const void* src) {
    asm volatile("cp.async.cg.shared.global [%0], [%1], 16;" :: "r"(dst), "l"(src));
}
__device__ __forceinline__ uint32_t packh(float a, float b) {
    __half2 h = __floats2half2_rn(a, b);
    return *reinterpret_cast<uint32_t*>(&h);
}

__global__ __launch_bounds__(256, 3)
void mma_kernel(const float* __restrict__ A)
{
    extern __shared__ char smem[];
    const uint32_t smb = (uint32_t)__cvta_generic_to_shared(smem);

    const int tid  = threadIdx.x;
    const int wid  = tid >> 5;
    const int lane = tid & 31;
    const int wm   = wid >> 2;                       // 2 m-groups of 32
    const int ng   = (wid < 4) ? wid : 7 - wid;      // SMSP-balanced n-group
    const int s0   = blockIdx.x * 64;
    const int g    = blockIdx.y;

    // uniform-cost quantum range: quanta = (pair p, a-chunk), 512 per s-tile
    const int qs  = (g * 512) / KSPLIT;
    const int qe  = ((g + 1) * 512) / KSPLIT;
    const int NIT = 2 * (qe - qs);                   // 36 or 38

    // A loader: thread t covers row t>>2, fp32 cols [(t&3)*16, +16)
    const int arowL = tid >> 2;                      // 0..63
    const int af4   = (tid & 3) * 16;                // fp32 col base
    // B loader: 2 threads per row
    const int brow  = tid >> 1;                      // 0..127
    const int bhalf = tid & 1;

    // ldmatrix geometry (16B-unit XOR swizzle on 128B rows)
    const int arow  = wm*32 + (lane & 15);
    const int axor  = arow & 7;
    const int asel  = lane >> 4;
    const int browl = 8*ng + (lane & 7) + 32*((lane >> 4) & 1);
    const int bxor  = lane & 7;
    const int bsel  = (lane >> 3) & 1;

    float acc[2][4][4];
#pragma unroll
    for (int im = 0; im < 2; im++)
#pragma unroll
        for (int j = 0; j < 4; j++)
#pragma unroll
            for (int c = 0; c < 4; c++) acc[im][j][c] = 0.f;

    // iter it -> (k, a0): q = qs + it/2; pair p = q>>3; a-chunk = q&7
    auto kofit = [&](int it, int& k, int& a0) {
        const int q = qs + (it >> 1);
        const int p = q >> 3;
        k  = (it & 1) ? (127 - p) : p;
        a0 = (q & 7) << 6;
    };

    float rF[16];

    auto ldgF = [&](int k, int a0) {
        const float* p = A + ((size_t)k*1024 + s0 + arowL)*512 + a0 + af4;
#pragma unroll
        for (int jj = 0; jj < 4; jj++) {
            float4 v = *reinterpret_cast<const float4*>(p + jj*4);
            rF[4*jj+0] = v.x; rF[4*jj+1] = v.y; rF[4*jj+2] = v.z; rF[4*jj+3] = v.w;
        }
    };
    auto cvtstsA = [&](int buf) {
        uint4 w0 = make_uint4(packh(rF[0],  rF[1]),  packh(rF[2],  rF[3]),
                              packh(rF[4],  rF[5]),  packh(rF[6],  rF[7]));
        uint4 w1 = make_uint4(packh(rF[8],  rF[9]),  packh(rF[10], rF[11]),
                              packh(rF[12], rF[13]), packh(rF[14], rF[15]));
        const int u0 = (tid & 3) * 2;
        const int rx = arowL & 7;
        char* base = smem + buf*ATILE + arowL*128;
        *reinterpret_cast<uint4*>(base + (((u0    ) ^ rx) << 4)) = w0;
        *reinterpret_cast<uint4*>(base + (((u0 + 1) ^ rx) << 4)) = w1;
    };
    auto cpB = [&](int k, int a0, int buf) {
        const __half* src = g_Uf + (size_t)(brow + 128 - k)*512 + a0;
        const uint32_t dst = smb + BOFF0 + buf*BTILE + brow*128;
        const int rx = brow & 7;
#pragma unroll
        for (int c = 0; c < 4; c++) {
            const int u = bhalf*4 + c;
            cpa16(dst + ((u ^ rx) << 4), src + u*8);
        }
    };

    // ---- prologue: stage iter 0 ----
    {
        int k0, a00; kofit(0, k0, a00);
        ldgF(k0, a00); cvtstsA(0);
        cpB(k0, a00, 0);
        asm volatile("cp.async.commit_group;" ::: "memory");
    }

    // ---- main loop (NIT iterations, K=64 each) ----
    for (int it = 0; it < NIT; it++) {
        const int buf = it & 1;
        int k, a0; kofit(it, k, a0);

        asm volatile("cp.async.wait_group 0;" ::: "memory");
        __syncthreads();

        if (it + 1 < NIT) {
            int kn, a0n; kofit(it + 1, kn, a0n);
            ldgF(kn, a0n);
            cpB(kn, a0n, buf ^ 1);
            asm volatile("cp.async.commit_group;" ::: "memory");
        }

        // causal liveness: n8-tile j covers n in [(4j+ng)*8, +8)
        bool lv[4];
#pragma unroll
        for (int j = 0; j < 4; j++)
            lv[j] = (k < ((4*j + ng) << 3) + 8);
        bool lp[2];
#pragma unroll
        for (int p = 0; p < 2; p++)
            lp[p] = lv[2*p + 1];      // lv monotone increasing in j

        const uint32_t ab = smb + buf*ATILE + arow*128;
        const uint32_t bb = smb + BOFF0 + buf*BTILE + browl*128;
#pragma unroll
        for (int kb = 0; kb < 4; kb++) {
            uint32_t ah[2][4], uf[2][4];
            const int au = 2*kb + asel;
            ldmx4(ah[0], ab +        ((au ^ axor) << 4));
            ldmx4(ah[1], ab + 2048 + ((au ^ axor) << 4));
            const int bu = 2*kb + bsel;
            const uint32_t bsw = (uint32_t)((bu ^ bxor) << 4);
#pragma unroll
            for (int p = 0; p < 2; p++)
                if (lp[p]) ldmx4(uf[p], bb + p*8192 + bsw);
#pragma unroll
            for (int im = 0; im < 2; im++)
#pragma unroll
                for (int j = 0; j < 4; j++)
                    if (lv[j])
                        mma16816(acc[im][j], ah[im], &uf[j >> 1][(j & 1) * 2]);
        }

        if (it + 1 < NIT) cvtstsA(buf ^ 1);    // LDG latency hidden by body
    }

    // ---- epilogue: write split-K partials [g][t][s] ----
    float* pb = g_partial + (size_t)g * 131072;
    const int sidx = s0 + wm*32 + (lane >> 2);
#pragma unroll
    for (int im = 0; im < 2; im++) {
        const int sr = sidx + im*16;
#pragma unroll
        for (int j = 0; j < 4; j++) {
            const int n = ((4*j + ng) << 3) + (lane & 3) * 2;
            pb[(size_t)n      * 1024 + sr]     = acc[im][j][0];
            pb[(size_t)(n+1)  * 1024 + sr]     = acc[im][j][1];
            pb[(size_t)n      * 1024 + sr + 8] = acc[im][j][2];
            pb[(size_t)(n+1)  * 1024 + sr + 8] = acc[im][j][3];
        }
    }
}

__global__ __launch_bounds__(256) void reduce_kernel(float* __restrict__ out)
{
    int i = blockIdx.x*256 + threadIdx.x;   // 0..131071 floats
    float s = 0.f;
#pragma unroll
    for (int gg = 0; gg < KSPLIT; gg++)
        s += g_partial[(size_t)gg*131072 + i];
    out[i] = s;
}

extern "C" void kernel_launch(void* const* d_in, const int* in_sizes, int n_in,
                              void* d_out, int out_size)
{
    const float* us = (const float*)d_in[0];   // [128, 512]
    const float* A  = (const float*)d_in[1];   // [128, 1024, 512]
    if (n_in >= 2 && in_sizes[0] > in_sizes[1]) {
        const float* t = us; us = A; A = t;
    }
    cudaFuncSetAttribute(mma_kernel, cudaFuncAttributeMaxDynamicSharedMemorySize, SMEMT);

    prep_kernel<<<512, 256>>>(us);
    dummy_kernel<<<1, 1>>>();
    dummy_kernel<<<1, 1>>>();
    mma_kernel<<<dim3(16, KSPLIT), 256, SMEMT>>>(A);
    reduce_kernel<<<512, 256>>>((float*)d_out);
}